// round 2
// baseline (speedup 1.0000x reference)
#include <cuda_runtime.h>
#include <cstdint>

// ContrastiveLoss: input_[N=4, E=16, H=768, W=768] f32, target[N,H,W] int32-or-int64, C=32.
// Pipeline (graph-capturable, alloc-free):
//   k_zero    : zero accumulators
//   k_detect  : detect target dtype (int32 vs int64) from first row (deterministic pattern)
//   k_convert : labels -> uint8 buffer (2.4MB for later passes)
//   k_pass1   : segment sums[n,c,e] + counts[n,c] via lane-private shared bins (no hot-loop atomics)
//   k_stats   : means + pairwise distance term + regularizer (tiny)
//   k_var     : variance term = sum_p hinge(d_p)^2 * inv_count[lab_p] (scalar reduction, no 2nd segsum)
//   k_final   : combine -> d_out[0]

#define N_IMG 4
#define E_CH  16
#define CMAX  32
#define PAD   33

__device__ float g_sums [N_IMG * CMAX * E_CH];
__device__ float g_cnts [N_IMG * CMAX];
__device__ float g_means[N_IMG * CMAX * E_CH];
__device__ float g_var  [N_IMG];
__device__ float g_aux  [N_IMG];
__device__ int   g_is64;
__device__ __align__(16) unsigned char g_lab[N_IMG * 768 * 768];

// ---------------------------------------------------------------------------
__global__ void k_zero() {
    int t = blockIdx.x * blockDim.x + threadIdx.x;
    if (t < N_IMG * CMAX * E_CH) g_sums[t] = 0.f;
    if (t < N_IMG * CMAX)        g_cnts[t] = 0.f;
    if (t < N_IMG)             { g_var[t] = 0.f; g_aux[t] = 0.f; }
}

// ---------------------------------------------------------------------------
// Dataset guarantees target[0,0,0:32] = 0..31. If stored as int64 (LE), the odd
// 32-bit words of the first 64 words are all zero; if int32, word[1] == 1 != 0.
__global__ void k_detect(const unsigned int* __restrict__ tgt) {
    if (threadIdx.x == 0 && blockIdx.x == 0) {
        int is64 = 1;
        #pragma unroll
        for (int i = 1; i < 64; i += 2)
            if (tgt[i] != 0u) is64 = 0;
        g_is64 = is64;
    }
}

// ---------------------------------------------------------------------------
// Labels -> uint8. Each thread handles 8 labels. Reads sized by detected dtype.
__global__ void k_convert(const void* __restrict__ tgt, int total) {
    int t = blockIdx.x * blockDim.x + threadIdx.x;
    if (t * 8 >= total) return;
    unsigned long long o;
    if (g_is64) {
        const longlong2* tp = reinterpret_cast<const longlong2*>(tgt) + (size_t)t * 4;
        longlong2 v0 = tp[0], v1 = tp[1], v2 = tp[2], v3 = tp[3];
        o =   ((unsigned long long)(v0.x & 0xff))
            | ((unsigned long long)(v0.y & 0xff) << 8)
            | ((unsigned long long)(v1.x & 0xff) << 16)
            | ((unsigned long long)(v1.y & 0xff) << 24)
            | ((unsigned long long)(v2.x & 0xff) << 32)
            | ((unsigned long long)(v2.y & 0xff) << 40)
            | ((unsigned long long)(v3.x & 0xff) << 48)
            | ((unsigned long long)(v3.y & 0xff) << 56);
    } else {
        const int4* tp = reinterpret_cast<const int4*>(tgt) + (size_t)t * 2;
        int4 v0 = tp[0], v1 = tp[1];
        o =   ((unsigned long long)(v0.x & 0xff))
            | ((unsigned long long)(v0.y & 0xff) << 8)
            | ((unsigned long long)(v0.z & 0xff) << 16)
            | ((unsigned long long)(v0.w & 0xff) << 24)
            | ((unsigned long long)(v1.x & 0xff) << 32)
            | ((unsigned long long)(v1.y & 0xff) << 40)
            | ((unsigned long long)(v1.z & 0xff) << 48)
            | ((unsigned long long)(v1.w & 0xff) << 56);
    }
    reinterpret_cast<unsigned long long*>(g_lab)[t] = o;
}

// ---------------------------------------------------------------------------
// Pass 1: segment sums + counts. Block = 16 warps; warp w streams channel w of
// an 8192-pixel chunk. Per warp, 16 lane-private [CMAX] bin copies; lanes l and
// l+16 share copy (l&15) but write in __syncwarp-separated phases: race-free.
#define CHUNK1 8192
__global__ void __launch_bounds__(512) k_pass1(const float* __restrict__ x,
                                               int C, int P) {
    __shared__ float bins[E_CH * 16 * PAD];
    __shared__ float cbin[16 * PAD];
    const int n = blockIdx.y;
    const int tid = threadIdx.x;
    const int w = tid >> 5, l = tid & 31;

    for (int i = tid; i < E_CH * 16 * PAD; i += 512) bins[i] = 0.f;
    for (int i = tid; i < 16 * PAD;        i += 512) cbin[i] = 0.f;
    __syncthreads();

    float* mb = bins + (w * 16 + (l & 15)) * PAD;
    float* mc = cbin + (l & 15) * PAD;

    const int base = blockIdx.x * CHUNK1;
    const float4* xp = reinterpret_cast<const float4*>(x + ((size_t)(n * E_CH + w)) * P + base);
    const uchar4* lp = reinterpret_cast<const uchar4*>(g_lab + (size_t)n * P + base);
    const int iters = (min(CHUNK1, P - base)) >> 7;

    for (int it = 0; it < iters; ++it) {
        int idx = it * 32 + l;
        float4 v = xp[idx];
        uchar4 lb = lp[idx];
        if (l < 16) {
            mb[lb.x] += v.x; mb[lb.y] += v.y; mb[lb.z] += v.z; mb[lb.w] += v.w;
            if (w == 0) { mc[lb.x] += 1.f; mc[lb.y] += 1.f; mc[lb.z] += 1.f; mc[lb.w] += 1.f; }
        }
        __syncwarp();
        if (l >= 16) {
            mb[lb.x] += v.x; mb[lb.y] += v.y; mb[lb.z] += v.z; mb[lb.w] += v.w;
            if (w == 0) { mc[lb.x] += 1.f; mc[lb.y] += 1.f; mc[lb.z] += 1.f; mc[lb.w] += 1.f; }
        }
        __syncwarp();
    }
    __syncthreads();

    if (l < C) {
        float s = 0.f;
        #pragma unroll
        for (int k = 0; k < 16; ++k) s += bins[(w * 16 + k) * PAD + l];
        atomicAdd(&g_sums[(n * CMAX + l) * E_CH + w], s);
        if (w == 0) {
            float sc = 0.f;
            #pragma unroll
            for (int k = 0; k < 16; ++k) sc += cbin[k * PAD + l];
            atomicAdd(&g_cnts[n * CMAX + l], sc);
        }
    }
}

// ---------------------------------------------------------------------------
__global__ void k_stats(int C) {
    __shared__ float sm[CMAX * E_CH];
    __shared__ float red[512], red2[512];
    const int tid = threadIdx.x;
    const float rep = 2.0f * 2.0f;   // 2 * DELTA_DIST

    for (int n = 0; n < N_IMG; ++n) {
        if (tid < C * E_CH) {
            int c = tid / E_CH;
            float cnt = fmaxf(g_cnts[n * CMAX + c], 1.f);
            float m = g_sums[n * CMAX * E_CH + tid] / cnt;
            sm[tid] = m;
            g_means[n * CMAX * E_CH + tid] = m;
        }
        __syncthreads();

        float dl = 0.f, rl = 0.f;
        for (int t = tid; t < C * C; t += 512) {
            int i = t / C, j = t - i * C;
            if (i != j) {
                float s = 0.f;
                #pragma unroll
                for (int e = 0; e < E_CH; ++e) {
                    float d = sm[i * E_CH + e] - sm[j * E_CH + e];
                    s += d * d;
                }
                float dist = sqrtf(fmaxf(s, 1e-12f));
                float h = fmaxf(rep - dist, 0.f);
                dl += h * h;
            }
        }
        for (int c = tid; c < C; c += 512) {
            float s = 0.f;
            #pragma unroll
            for (int e = 0; e < E_CH; ++e) { float m = sm[c * E_CH + e]; s += m * m; }
            rl += sqrtf(fmaxf(s, 1e-12f));
        }
        red[tid] = dl; red2[tid] = rl;
        __syncthreads();
        for (int st = 256; st > 0; st >>= 1) {
            if (tid < st) { red[tid] += red[tid + st]; red2[tid] += red2[tid + st]; }
            __syncthreads();
        }
        if (tid == 0)
            g_aux[n] = red[0] / (float)(C * (C - 1)) + 0.001f * red2[0] / (float)C;
        __syncthreads();
    }
}

// ---------------------------------------------------------------------------
__global__ void __launch_bounds__(256) k_var(const float* __restrict__ x,
                                             int C, int P) {
    __shared__ float sm[CMAX * 17];
    __shared__ float sinv[CMAX];
    __shared__ float wred[8];
    const int n = blockIdx.y;
    const int tid = threadIdx.x;

    for (int i = tid; i < C * E_CH; i += 256) {
        int c = i >> 4, e = i & 15;
        sm[c * 17 + e] = g_means[(n * CMAX + c) * E_CH + e];
    }
    if (tid < C) sinv[tid] = 1.0f / fmaxf(g_cnts[n * CMAX + tid], 1.f);
    __syncthreads();

    float acc = 0.f;
    int p0 = blockIdx.x * 1024 + tid * 4;
    if (p0 < P) {
        uchar4 lb = *reinterpret_cast<const uchar4*>(g_lab + (size_t)n * P + p0);
        const float* xb = x + (size_t)n * E_CH * P + p0;
        int o0 = lb.x * 17, o1 = lb.y * 17, o2 = lb.z * 17, o3 = lb.w * 17;
        float d0 = 0.f, d1 = 0.f, d2 = 0.f, d3 = 0.f;
        #pragma unroll
        for (int e = 0; e < E_CH; ++e) {
            float4 v = *reinterpret_cast<const float4*>(xb + (size_t)e * P);
            float t0 = v.x - sm[o0 + e]; d0 += t0 * t0;
            float t1 = v.y - sm[o1 + e]; d1 += t1 * t1;
            float t2 = v.z - sm[o2 + e]; d2 += t2 * t2;
            float t3 = v.w - sm[o3 + e]; d3 += t3 * t3;
        }
        float dd, h;
        dd = sqrtf(fmaxf(d0, 1e-12f)); h = fmaxf(dd - 0.5f, 0.f); acc += h * h * sinv[lb.x];
        dd = sqrtf(fmaxf(d1, 1e-12f)); h = fmaxf(dd - 0.5f, 0.f); acc += h * h * sinv[lb.y];
        dd = sqrtf(fmaxf(d2, 1e-12f)); h = fmaxf(dd - 0.5f, 0.f); acc += h * h * sinv[lb.z];
        dd = sqrtf(fmaxf(d3, 1e-12f)); h = fmaxf(dd - 0.5f, 0.f); acc += h * h * sinv[lb.w];
    }

    #pragma unroll
    for (int off = 16; off; off >>= 1) acc += __shfl_down_sync(0xffffffffu, acc, off);
    if ((tid & 31) == 0) wred[tid >> 5] = acc;
    __syncthreads();
    if (tid < 8) {
        float v = wred[tid];
        #pragma unroll
        for (int off = 4; off; off >>= 1) v += __shfl_down_sync(0xffu, v, off);
        if (tid == 0) atomicAdd(&g_var[n], v);
    }
}

// ---------------------------------------------------------------------------
__global__ void k_final(float* __restrict__ out, int C) {
    if (threadIdx.x == 0 && blockIdx.x == 0) {
        float s = 0.f;
        #pragma unroll
        for (int n = 0; n < N_IMG; ++n)
            s += g_var[n] / (float)C + g_aux[n];
        out[0] = s / (float)N_IMG;
    }
}

// ---------------------------------------------------------------------------
extern "C" void kernel_launch(void* const* d_in, const int* in_sizes, int n_in,
                              void* d_out, int out_size) {
    const float* x   = (const float*)d_in[0];
    const void*  tgt = d_in[1];

    const int NP = in_sizes[1];      // N * H * W
    const int P  = NP / N_IMG;
    const int C  = CMAX;             // dataset guarantees all 32 labels present

    k_zero<<<8, 256>>>();
    k_detect<<<1, 32>>>((const unsigned int*)tgt);

    int cthreads = (NP + 7) / 8;
    k_convert<<<(cthreads + 255) / 256, 256>>>(tgt, NP);

    dim3 g1((P + CHUNK1 - 1) / CHUNK1, N_IMG);
    k_pass1<<<g1, 512>>>(x, C, P);

    k_stats<<<1, 512>>>(C);

    dim3 g3((P + 1023) / 1024, N_IMG);
    k_var<<<g3, 256>>>(x, C, P);

    k_final<<<1, 32>>>((float*)d_out, C);
}

// round 3
// speedup vs baseline: 1.3140x; 1.3140x over previous
#include <cuda_runtime.h>
#include <cstdint>

// ContrastiveLoss: input_[N=4, E=16, H=768, W=768] f32, target[N,H,W] i32/i64, C=32.
// Pipeline (graph-capturable, alloc-free, 5 launches):
//   k_convert : zero accumulators (block 0) + per-block dtype detect + labels -> uint8
//   k_pass1   : segment sums+counts, conflict-free transposed shared bins [c][lane]
//   k_stats   : means + distance term + regularizer (tiny)
//   k_var     : variance term with register-resident means gathered via shfl.idx
//   k_final   : combine -> d_out[0]

#define N_IMG 4
#define E_CH  16
#define CMAX  32
#define CHUNK1 4096

__device__ float g_sums [N_IMG * CMAX * E_CH];
__device__ float g_cnts [N_IMG * CMAX];
__device__ float g_means[N_IMG * CMAX * E_CH];
__device__ float g_var  [N_IMG];
__device__ float g_aux  [N_IMG];
__device__ __align__(16) unsigned char g_lab[N_IMG * 768 * 768];

// ---------------------------------------------------------------------------
// Labels -> uint8 (8 per thread). Block 0 also zeroes accumulators.
// Dtype detect: dataset guarantees target[0,0,0:32]=0..31, so for int64 (LE)
// the odd 32-bit words of the first 64 words are all zero; for int32 word[1]=1.
__global__ void __launch_bounds__(256) k_convert(const void* __restrict__ tgt, int total) {
    __shared__ int s_is64;
    if (blockIdx.x == 0) {
        for (int i = threadIdx.x; i < N_IMG * CMAX * E_CH; i += 256) g_sums[i] = 0.f;
        if (threadIdx.x < N_IMG * CMAX) g_cnts[threadIdx.x] = 0.f;
        if (threadIdx.x < N_IMG) g_var[threadIdx.x] = 0.f;
    }
    if (threadIdx.x == 0) {
        const unsigned int* u = (const unsigned int*)tgt;
        int is64 = 1;
        #pragma unroll
        for (int i = 1; i < 64; i += 2)
            if (u[i] != 0u) is64 = 0;
        s_is64 = is64;
    }
    __syncthreads();

    int t = blockIdx.x * 256 + threadIdx.x;
    if (t * 8 >= total) return;
    unsigned long long o;
    if (s_is64) {
        const longlong2* tp = reinterpret_cast<const longlong2*>(tgt) + (size_t)t * 4;
        longlong2 v0 = tp[0], v1 = tp[1], v2 = tp[2], v3 = tp[3];
        o =   ((unsigned long long)(v0.x & 0xff))
            | ((unsigned long long)(v0.y & 0xff) << 8)
            | ((unsigned long long)(v1.x & 0xff) << 16)
            | ((unsigned long long)(v1.y & 0xff) << 24)
            | ((unsigned long long)(v2.x & 0xff) << 32)
            | ((unsigned long long)(v2.y & 0xff) << 40)
            | ((unsigned long long)(v3.x & 0xff) << 48)
            | ((unsigned long long)(v3.y & 0xff) << 56);
    } else {
        const int4* tp = reinterpret_cast<const int4*>(tgt) + (size_t)t * 2;
        int4 v0 = tp[0], v1 = tp[1];
        o =   ((unsigned long long)(v0.x & 0xff))
            | ((unsigned long long)(v0.y & 0xff) << 8)
            | ((unsigned long long)(v0.z & 0xff) << 16)
            | ((unsigned long long)(v0.w & 0xff) << 24)
            | ((unsigned long long)(v1.x & 0xff) << 32)
            | ((unsigned long long)(v1.y & 0xff) << 40)
            | ((unsigned long long)(v1.z & 0xff) << 48)
            | ((unsigned long long)(v1.w & 0xff) << 56);
    }
    reinterpret_cast<unsigned long long*>(g_lab)[t] = o;
}

// ---------------------------------------------------------------------------
// Pass 1: segment sums + counts.
// 17 warps: warp w<16 streams channel w; warp 16 streams counts.
// Bins transposed: bins[warp][c][lane], row stride 32 -> bank == lane, so the
// random label NEVER causes a bank conflict. Lane-private columns: race-free.
__global__ void __launch_bounds__(544) k_pass1(const float* __restrict__ x, int P) {
    __shared__ float bins[17 * CMAX * 32];
    const int n = blockIdx.y;
    const int tid = threadIdx.x;
    const int w = tid >> 5, l = tid & 31;

    for (int i = tid * 4; i < 17 * CMAX * 32; i += 544 * 4)
        *reinterpret_cast<float4*>(bins + i) = make_float4(0.f, 0.f, 0.f, 0.f);
    __syncthreads();

    float* mb = bins + w * (CMAX * 32);

    const int base = blockIdx.x * CHUNK1;
    const uchar4* lp = reinterpret_cast<const uchar4*>(g_lab + (size_t)n * P + base);
    const int iters = (min(CHUNK1, P - base)) >> 7;   // 128 pixels per warp-iter

    if (w < 16) {
        const float4* xp = reinterpret_cast<const float4*>(x + ((size_t)(n * E_CH + w)) * P + base);
        for (int it = 0; it < iters; ++it) {
            int idx = it * 32 + l;
            float4 v = xp[idx];
            uchar4 lb = lp[idx];
            mb[lb.x * 32 + l] += v.x;
            mb[lb.y * 32 + l] += v.y;
            mb[lb.z * 32 + l] += v.z;
            mb[lb.w * 32 + l] += v.w;
        }
    } else {
        for (int it = 0; it < iters; ++it) {
            int idx = it * 32 + l;
            uchar4 lb = lp[idx];
            mb[lb.x * 32 + l] += 1.f;
            mb[lb.y * 32 + l] += 1.f;
            mb[lb.z * 32 + l] += 1.f;
            mb[lb.w * 32 + l] += 1.f;
        }
    }
    __syncwarp();

    // Flush: lane l sums cluster l's row with rotated reads (bank = (l+j)&31).
    float tot = 0.f;
    #pragma unroll
    for (int j = 0; j < 32; ++j)
        tot += mb[l * 32 + ((l + j) & 31)];
    if (w < 16) atomicAdd(&g_sums[(n * CMAX + l) * E_CH + w], tot);
    else        atomicAdd(&g_cnts[n * CMAX + l], tot);
}

// ---------------------------------------------------------------------------
__global__ void __launch_bounds__(512) k_stats() {
    __shared__ float sm[CMAX * E_CH];
    __shared__ float red[512], red2[512];
    const int tid = threadIdx.x;
    const int C = CMAX;
    const float rep = 2.0f * 2.0f;   // 2 * DELTA_DIST

    for (int n = 0; n < N_IMG; ++n) {
        if (tid < C * E_CH) {
            int c = tid / E_CH;
            float cnt = fmaxf(g_cnts[n * CMAX + c], 1.f);
            float m = g_sums[n * CMAX * E_CH + tid] / cnt;
            sm[tid] = m;
            g_means[n * CMAX * E_CH + tid] = m;
        }
        __syncthreads();

        float dl = 0.f, rl = 0.f;
        for (int t = tid; t < C * C; t += 512) {
            int i = t / C, j = t - i * C;
            if (i != j) {
                float s = 0.f;
                #pragma unroll
                for (int e = 0; e < E_CH; ++e) {
                    float d = sm[i * E_CH + e] - sm[j * E_CH + e];
                    s += d * d;
                }
                float dist = sqrtf(fmaxf(s, 1e-12f));
                float h = fmaxf(rep - dist, 0.f);
                dl += h * h;
            }
        }
        if (tid < C) {
            float s = 0.f;
            #pragma unroll
            for (int e = 0; e < E_CH; ++e) { float m = sm[tid * E_CH + e]; s += m * m; }
            rl = sqrtf(fmaxf(s, 1e-12f));
        }
        red[tid] = dl; red2[tid] = rl;
        __syncthreads();
        for (int st = 256; st > 0; st >>= 1) {
            if (tid < st) { red[tid] += red[tid + st]; red2[tid] += red2[tid + st]; }
            __syncthreads();
        }
        if (tid == 0)
            g_aux[n] = red[0] / (float)(C * (C - 1)) + 0.001f * red2[0] / (float)C;
        __syncthreads();
    }
}

// ---------------------------------------------------------------------------
// Variance term. Lane l of every warp holds mean[l][0..15] in registers and
// inv_count[l]; arbitrary-cluster gathers are shfl.idx (conflict-free, 1 cyc).
__global__ void __launch_bounds__(256) k_var(const float* __restrict__ x, int P) {
    __shared__ float wred[8];
    const int n = blockIdx.y;
    const int tid = threadIdx.x;
    const int l = tid & 31;

    float m[E_CH];
    {
        const float4* gm = reinterpret_cast<const float4*>(g_means + (n * CMAX + l) * E_CH);
        float4* mm = reinterpret_cast<float4*>(m);
        mm[0] = gm[0]; mm[1] = gm[1]; mm[2] = gm[2]; mm[3] = gm[3];
    }
    float sinv = 1.0f / fmaxf(g_cnts[n * CMAX + l], 1.f);

    const int p0 = blockIdx.x * 1024 + tid * 4;
    uchar4 lb = *reinterpret_cast<const uchar4*>(g_lab + (size_t)n * P + p0);
    const int c0 = lb.x, c1 = lb.y, c2 = lb.z, c3 = lb.w;
    const float* xb = x + (size_t)n * E_CH * P + p0;

    float d0 = 0.f, d1 = 0.f, d2 = 0.f, d3 = 0.f;
    #pragma unroll
    for (int e = 0; e < E_CH; ++e) {
        float4 v = *reinterpret_cast<const float4*>(xb + (size_t)e * P);
        float t;
        t = v.x - __shfl_sync(0xffffffffu, m[e], c0); d0 += t * t;
        t = v.y - __shfl_sync(0xffffffffu, m[e], c1); d1 += t * t;
        t = v.z - __shfl_sync(0xffffffffu, m[e], c2); d2 += t * t;
        t = v.w - __shfl_sync(0xffffffffu, m[e], c3); d3 += t * t;
    }

    float acc = 0.f, dd, h;
    dd = sqrtf(fmaxf(d0, 1e-12f)); h = fmaxf(dd - 0.5f, 0.f);
    acc += h * h * __shfl_sync(0xffffffffu, sinv, c0);
    dd = sqrtf(fmaxf(d1, 1e-12f)); h = fmaxf(dd - 0.5f, 0.f);
    acc += h * h * __shfl_sync(0xffffffffu, sinv, c1);
    dd = sqrtf(fmaxf(d2, 1e-12f)); h = fmaxf(dd - 0.5f, 0.f);
    acc += h * h * __shfl_sync(0xffffffffu, sinv, c2);
    dd = sqrtf(fmaxf(d3, 1e-12f)); h = fmaxf(dd - 0.5f, 0.f);
    acc += h * h * __shfl_sync(0xffffffffu, sinv, c3);

    #pragma unroll
    for (int off = 16; off; off >>= 1) acc += __shfl_down_sync(0xffffffffu, acc, off);
    if (l == 0) wred[tid >> 5] = acc;
    __syncthreads();
    if (tid < 8) {
        float v = wred[tid];
        #pragma unroll
        for (int off = 4; off; off >>= 1) v += __shfl_down_sync(0xffu, v, off);
        if (tid == 0) atomicAdd(&g_var[n], v);
    }
}

// ---------------------------------------------------------------------------
__global__ void k_final(float* __restrict__ out) {
    if (threadIdx.x == 0 && blockIdx.x == 0) {
        float s = 0.f;
        #pragma unroll
        for (int n = 0; n < N_IMG; ++n)
            s += g_var[n] / (float)CMAX + g_aux[n];
        out[0] = s / (float)N_IMG;
    }
}

// ---------------------------------------------------------------------------
extern "C" void kernel_launch(void* const* d_in, const int* in_sizes, int n_in,
                              void* d_out, int out_size) {
    const float* x   = (const float*)d_in[0];
    const void*  tgt = d_in[1];

    const int NP = in_sizes[1];      // N * H * W
    const int P  = NP / N_IMG;

    int cthreads = (NP + 7) / 8;
    k_convert<<<(cthreads + 255) / 256, 256>>>(tgt, NP);

    dim3 g1((P + CHUNK1 - 1) / CHUNK1, N_IMG);
    k_pass1<<<g1, 544>>>(x, P);

    k_stats<<<1, 512>>>();

    dim3 g3((P + 1023) / 1024, N_IMG);
    k_var<<<g3, 256>>>(x, P);

    k_final<<<1, 32>>>((float*)d_out);
}

// round 4
// speedup vs baseline: 1.3400x; 1.0198x over previous
#include <cuda_runtime.h>
#include <cstdint>

// ContrastiveLoss: input_[N=4, E=16, H=768, W=768] f32, target[N,H,W] i32/i64, C=32.
// Launches: k_convert (labels->u8 + counts), k_pass1 (segment sums, MLP-4 unrolled),
//           k_stats, k_var x4 (images 3..0 for L2 reuse), k_final (+ cleanup re-zero).

#define N_IMG 4
#define E_CH  16
#define CMAX  32
#define CHUNK1 4096

__device__ float g_sums [N_IMG * CMAX * E_CH];
__device__ float g_cnts [N_IMG * CMAX];
__device__ float g_means[N_IMG * CMAX * E_CH];
__device__ float g_var  [N_IMG];
__device__ float g_aux  [N_IMG];
__device__ __align__(16) unsigned char g_lab[N_IMG * 768 * 768];

// ---------------------------------------------------------------------------
// Labels -> uint8 (8/thread) + per-block count histogram -> g_cnts atomics.
// Dtype detect per block: dataset sets target[0,0,0:32]=0..31, so for int64 (LE)
// odd 32-bit words of the first 64 words are all zero; for int32 word[1]==1.
__global__ void __launch_bounds__(256) k_convert(const void* __restrict__ tgt,
                                                 int total, int P) {
    __shared__ float cnt[8 * CMAX * 32];    // [warp][c][lane], bank==lane: conflict-free
    __shared__ float sbuf[8 * 32];
    __shared__ int s_is64;
    const int tid = threadIdx.x;
    const int w = tid >> 5, l = tid & 31;

    for (int i = tid * 4; i < 8 * CMAX * 32; i += 1024)
        *reinterpret_cast<float4*>(cnt + i) = make_float4(0.f, 0.f, 0.f, 0.f);
    if (tid == 0) {
        const unsigned int* u = (const unsigned int*)tgt;
        int is64 = 1;
        #pragma unroll
        for (int i = 1; i < 64; i += 2)
            if (u[i] != 0u) is64 = 0;
        s_is64 = is64;
    }
    __syncthreads();

    const int t = blockIdx.x * 256 + tid;
    unsigned int b[8];
    if (s_is64) {
        const longlong2* tp = reinterpret_cast<const longlong2*>(tgt) + (size_t)t * 4;
        longlong2 v0 = tp[0], v1 = tp[1], v2 = tp[2], v3 = tp[3];
        b[0] = (unsigned int)(v0.x & 0xff); b[1] = (unsigned int)(v0.y & 0xff);
        b[2] = (unsigned int)(v1.x & 0xff); b[3] = (unsigned int)(v1.y & 0xff);
        b[4] = (unsigned int)(v2.x & 0xff); b[5] = (unsigned int)(v2.y & 0xff);
        b[6] = (unsigned int)(v3.x & 0xff); b[7] = (unsigned int)(v3.y & 0xff);
    } else {
        const int4* tp = reinterpret_cast<const int4*>(tgt) + (size_t)t * 2;
        int4 v0 = tp[0], v1 = tp[1];
        b[0] = (unsigned int)(v0.x & 0xff); b[1] = (unsigned int)(v0.y & 0xff);
        b[2] = (unsigned int)(v0.z & 0xff); b[3] = (unsigned int)(v0.w & 0xff);
        b[4] = (unsigned int)(v1.x & 0xff); b[5] = (unsigned int)(v1.y & 0xff);
        b[6] = (unsigned int)(v1.z & 0xff); b[7] = (unsigned int)(v1.w & 0xff);
    }
    unsigned long long o =
          (unsigned long long)b[0]        | ((unsigned long long)b[1] << 8)
        | ((unsigned long long)b[2] << 16) | ((unsigned long long)b[3] << 24)
        | ((unsigned long long)b[4] << 32) | ((unsigned long long)b[5] << 40)
        | ((unsigned long long)b[6] << 48) | ((unsigned long long)b[7] << 56);
    reinterpret_cast<unsigned long long*>(g_lab)[t] = o;

    float* mc = cnt + w * (CMAX * 32);
    #pragma unroll
    for (int i = 0; i < 8; ++i) mc[b[i] * 32 + l] += 1.f;
    __syncthreads();

    // stage 1: per-warp flush with rotated reads
    float tot = 0.f;
    #pragma unroll
    for (int j = 0; j < 32; ++j) tot += mc[l * 32 + ((l + j) & 31)];
    sbuf[w * 32 + l] = tot;
    __syncthreads();

    // stage 2: warp 0 reduces 8 warps, one atomic per cluster per block
    if (w == 0) {
        float s = 0.f;
        #pragma unroll
        for (int k = 0; k < 8; ++k) s += sbuf[k * 32 + l];
        const int n = (blockIdx.x * 2048) / P;
        atomicAdd(&g_cnts[n * CMAX + l], s);
    }
}

// ---------------------------------------------------------------------------
// Pass 1: segment sums. 16 warps; warp w streams channel w. Transposed bins
// [c][lane] (bank==lane, conflict-free, lane-private: race-free). Manual 4x
// unroll with front-batched loads -> MLP=4, hides DRAM latency.
__global__ void __launch_bounds__(512) k_pass1(const float* __restrict__ x, int P) {
    __shared__ float bins[E_CH * CMAX * 32];   // 64KB
    const int n = blockIdx.y;
    const int tid = threadIdx.x;
    const int w = tid >> 5, l = tid & 31;

    for (int i = tid * 4; i < E_CH * CMAX * 32; i += 512 * 4)
        *reinterpret_cast<float4*>(bins + i) = make_float4(0.f, 0.f, 0.f, 0.f);
    __syncthreads();

    float* mb = bins + w * (CMAX * 32);

    const int base = blockIdx.x * CHUNK1;
    const float4* xp = reinterpret_cast<const float4*>(x + ((size_t)(n * E_CH + w)) * P + base);
    const unsigned int* lp = reinterpret_cast<const unsigned int*>(g_lab + (size_t)n * P + base);
    const int iters = CHUNK1 >> 7;   // 32, multiple of 4

    for (int it = 0; it < iters; it += 4) {
        const int i0 = it * 32 + l;
        // front-batch: 4 independent 128-bit loads + 4 label words in flight
        float4 v0 = xp[i0];
        float4 v1 = xp[i0 + 32];
        float4 v2 = xp[i0 + 64];
        float4 v3 = xp[i0 + 96];
        unsigned int u0 = lp[i0], u1 = lp[i0 + 32], u2 = lp[i0 + 64], u3 = lp[i0 + 96];

        mb[(u0 & 0xffu) * 32 + l]         += v0.x;
        mb[((u0 >> 8) & 0xffu) * 32 + l]  += v0.y;
        mb[((u0 >> 16) & 0xffu) * 32 + l] += v0.z;
        mb[(u0 >> 24) * 32 + l]           += v0.w;

        mb[(u1 & 0xffu) * 32 + l]         += v1.x;
        mb[((u1 >> 8) & 0xffu) * 32 + l]  += v1.y;
        mb[((u1 >> 16) & 0xffu) * 32 + l] += v1.z;
        mb[(u1 >> 24) * 32 + l]           += v1.w;

        mb[(u2 & 0xffu) * 32 + l]         += v2.x;
        mb[((u2 >> 8) & 0xffu) * 32 + l]  += v2.y;
        mb[((u2 >> 16) & 0xffu) * 32 + l] += v2.z;
        mb[(u2 >> 24) * 32 + l]           += v2.w;

        mb[(u3 & 0xffu) * 32 + l]         += v3.x;
        mb[((u3 >> 8) & 0xffu) * 32 + l]  += v3.y;
        mb[((u3 >> 16) & 0xffu) * 32 + l] += v3.z;
        mb[(u3 >> 24) * 32 + l]           += v3.w;
    }
    __syncwarp();

    float tot = 0.f;
    #pragma unroll
    for (int j = 0; j < 32; ++j)
        tot += mb[l * 32 + ((l + j) & 31)];
    atomicAdd(&g_sums[(n * CMAX + l) * E_CH + w], tot);
}

// ---------------------------------------------------------------------------
__global__ void __launch_bounds__(512) k_stats() {
    __shared__ float sm[CMAX * E_CH];
    __shared__ float red[512], red2[512];
    const int tid = threadIdx.x;
    const int C = CMAX;
    const float rep = 2.0f * 2.0f;   // 2 * DELTA_DIST

    for (int n = 0; n < N_IMG; ++n) {
        if (tid < C * E_CH) {
            int c = tid / E_CH;
            float cnt = fmaxf(g_cnts[n * CMAX + c], 1.f);
            float m = g_sums[n * CMAX * E_CH + tid] / cnt;
            sm[tid] = m;
            g_means[n * CMAX * E_CH + tid] = m;
        }
        __syncthreads();

        float dl = 0.f, rl = 0.f;
        for (int t = tid; t < C * C; t += 512) {
            int i = t / C, j = t - i * C;
            if (i != j) {
                float s = 0.f;
                #pragma unroll
                for (int e = 0; e < E_CH; ++e) {
                    float d = sm[i * E_CH + e] - sm[j * E_CH + e];
                    s += d * d;
                }
                float dist = sqrtf(fmaxf(s, 1e-12f));
                float h = fmaxf(rep - dist, 0.f);
                dl += h * h;
            }
        }
        if (tid < C) {
            float s = 0.f;
            #pragma unroll
            for (int e = 0; e < E_CH; ++e) { float m = sm[tid * E_CH + e]; s += m * m; }
            rl = sqrtf(fmaxf(s, 1e-12f));
        }
        red[tid] = dl; red2[tid] = rl;
        __syncthreads();
        for (int st = 256; st > 0; st >>= 1) {
            if (tid < st) { red[tid] += red[tid + st]; red2[tid] += red2[tid + st]; }
            __syncthreads();
        }
        if (tid == 0)
            g_aux[n] = red[0] / (float)(C * (C - 1)) + 0.001f * red2[0] / (float)C;
        __syncthreads();
    }
}

// ---------------------------------------------------------------------------
// Variance term for one image (n passed; launched 3,2,1,0 for L2 reuse).
// Lane l holds mean[l][*] + inv_count[l] in registers; gathers via shfl.idx.
__global__ void __launch_bounds__(256) k_var(const float* __restrict__ x, int P, int n) {
    __shared__ float wred[8];
    const int tid = threadIdx.x;
    const int l = tid & 31;

    float m[E_CH];
    {
        const float4* gm = reinterpret_cast<const float4*>(g_means + (n * CMAX + l) * E_CH);
        float4* mm = reinterpret_cast<float4*>(m);
        mm[0] = gm[0]; mm[1] = gm[1]; mm[2] = gm[2]; mm[3] = gm[3];
    }
    float sinv = 1.0f / fmaxf(g_cnts[n * CMAX + l], 1.f);

    const int p0 = blockIdx.x * 1024 + tid * 4;
    unsigned int u = *reinterpret_cast<const unsigned int*>(g_lab + (size_t)n * P + p0);
    const int c0 = u & 0xffu, c1 = (u >> 8) & 0xffu, c2 = (u >> 16) & 0xffu, c3 = u >> 24;
    const float* xb = x + (size_t)n * E_CH * P + p0;

    float d0 = 0.f, d1 = 0.f, d2 = 0.f, d3 = 0.f;
    #pragma unroll
    for (int e = 0; e < E_CH; ++e) {
        float4 v = *reinterpret_cast<const float4*>(xb + (size_t)e * P);
        float t;
        t = v.x - __shfl_sync(0xffffffffu, m[e], c0); d0 += t * t;
        t = v.y - __shfl_sync(0xffffffffu, m[e], c1); d1 += t * t;
        t = v.z - __shfl_sync(0xffffffffu, m[e], c2); d2 += t * t;
        t = v.w - __shfl_sync(0xffffffffu, m[e], c3); d3 += t * t;
    }

    float acc = 0.f, dd, h;
    dd = sqrtf(fmaxf(d0, 1e-12f)); h = fmaxf(dd - 0.5f, 0.f);
    acc += h * h * __shfl_sync(0xffffffffu, sinv, c0);
    dd = sqrtf(fmaxf(d1, 1e-12f)); h = fmaxf(dd - 0.5f, 0.f);
    acc += h * h * __shfl_sync(0xffffffffu, sinv, c1);
    dd = sqrtf(fmaxf(d2, 1e-12f)); h = fmaxf(dd - 0.5f, 0.f);
    acc += h * h * __shfl_sync(0xffffffffu, sinv, c2);
    dd = sqrtf(fmaxf(d3, 1e-12f)); h = fmaxf(dd - 0.5f, 0.f);
    acc += h * h * __shfl_sync(0xffffffffu, sinv, c3);

    #pragma unroll
    for (int off = 16; off; off >>= 1) acc += __shfl_down_sync(0xffffffffu, acc, off);
    if (l == 0) wred[tid >> 5] = acc;
    __syncthreads();
    if (tid < 8) {
        float v = wred[tid];
        #pragma unroll
        for (int off = 4; off; off >>= 1) v += __shfl_down_sync(0xffu, v, off);
        if (tid == 0) atomicAdd(&g_var[n], v);
    }
}

// ---------------------------------------------------------------------------
// Final combine + cleanup: re-zero accumulators so the next graph replay sees
// the same initial state (device globals start zeroed at module load).
__global__ void __launch_bounds__(256) k_final(float* __restrict__ out) {
    const int tid = threadIdx.x;
    if (tid == 0) {
        float s = 0.f;
        #pragma unroll
        for (int n = 0; n < N_IMG; ++n)
            s += g_var[n] / (float)CMAX + g_aux[n];
        out[0] = s / (float)N_IMG;
    }
    __syncthreads();
    for (int i = tid; i < N_IMG * CMAX * E_CH; i += 256) g_sums[i] = 0.f;
    if (tid < N_IMG * CMAX) g_cnts[tid] = 0.f;
    if (tid < N_IMG) g_var[tid] = 0.f;
}

// ---------------------------------------------------------------------------
extern "C" void kernel_launch(void* const* d_in, const int* in_sizes, int n_in,
                              void* d_out, int out_size) {
    const float* x   = (const float*)d_in[0];
    const void*  tgt = d_in[1];

    const int NP = in_sizes[1];      // N * H * W
    const int P  = NP / N_IMG;

    k_convert<<<(NP + 2047) / 2048, 256>>>(tgt, NP, P);

    dim3 g1((P + CHUNK1 - 1) / CHUNK1, N_IMG);
    k_pass1<<<g1, 512>>>(x, P);

    k_stats<<<1, 512>>>();

    const int vblocks = (P + 1023) / 1024;
    for (int n = N_IMG - 1; n >= 0; --n)
        k_var<<<vblocks, 256>>>(x, P, n);

    k_final<<<1, 256>>>((float*)d_out);
}

// round 5
// speedup vs baseline: 1.6474x; 1.2294x over previous
#include <cuda_runtime.h>
#include <cstdint>

// ContrastiveLoss: input_[N=4, E=16, H=768, W=768] f32, target[N,H,W] i32/i64, C=32.
// 3 launches:
//   k_convert : labels -> uint8 + counts histogram
//   k_pass1   : segment sums (1 co-resident wave, MLP-8); LAST block computes
//               means + distance/reg terms (threadfence+counter handoff)
//   k_var     : variance term (merged, all images); LAST block writes d_out and
//               re-zeros accumulators for the next graph replay

#define N_IMG 4
#define E_CH  16
#define CMAX  32
#define CHUNK1 8192

__device__ float g_sums [N_IMG * CMAX * E_CH];
__device__ float g_cnts [N_IMG * CMAX];
__device__ float g_means[N_IMG * CMAX * E_CH];
__device__ float g_var  [N_IMG];
__device__ float g_aux  [N_IMG];
__device__ unsigned int g_done1;
__device__ unsigned int g_done2;
__device__ __align__(16) unsigned char g_lab[N_IMG * 768 * 768];

// ---------------------------------------------------------------------------
// Labels -> uint8 (8/thread) + per-block count histogram -> g_cnts atomics.
// Dtype detect: dataset sets target[0,0,0:32]=0..31, so for int64 (LE) the odd
// 32-bit words of the first 64 words are all zero; for int32 word[1]==1.
__global__ void __launch_bounds__(256) k_convert(const void* __restrict__ tgt,
                                                 int total, int P) {
    __shared__ float cnt[8 * CMAX * 32];    // [warp][c][lane], bank==lane: conflict-free
    __shared__ float sbuf[8 * 32];
    __shared__ int s_is64;
    const int tid = threadIdx.x;
    const int w = tid >> 5, l = tid & 31;

    for (int i = tid * 4; i < 8 * CMAX * 32; i += 1024)
        *reinterpret_cast<float4*>(cnt + i) = make_float4(0.f, 0.f, 0.f, 0.f);
    if (tid == 0) {
        const unsigned int* u = (const unsigned int*)tgt;
        int is64 = 1;
        #pragma unroll
        for (int i = 1; i < 64; i += 2)
            if (u[i] != 0u) is64 = 0;
        s_is64 = is64;
    }
    __syncthreads();

    const int t = blockIdx.x * 256 + tid;
    unsigned int b[8];
    if (s_is64) {
        const longlong2* tp = reinterpret_cast<const longlong2*>(tgt) + (size_t)t * 4;
        longlong2 v0 = tp[0], v1 = tp[1], v2 = tp[2], v3 = tp[3];
        b[0] = (unsigned int)(v0.x & 0xff); b[1] = (unsigned int)(v0.y & 0xff);
        b[2] = (unsigned int)(v1.x & 0xff); b[3] = (unsigned int)(v1.y & 0xff);
        b[4] = (unsigned int)(v2.x & 0xff); b[5] = (unsigned int)(v2.y & 0xff);
        b[6] = (unsigned int)(v3.x & 0xff); b[7] = (unsigned int)(v3.y & 0xff);
    } else {
        const int4* tp = reinterpret_cast<const int4*>(tgt) + (size_t)t * 2;
        int4 v0 = tp[0], v1 = tp[1];
        b[0] = (unsigned int)(v0.x & 0xff); b[1] = (unsigned int)(v0.y & 0xff);
        b[2] = (unsigned int)(v0.z & 0xff); b[3] = (unsigned int)(v0.w & 0xff);
        b[4] = (unsigned int)(v1.x & 0xff); b[5] = (unsigned int)(v1.y & 0xff);
        b[6] = (unsigned int)(v1.z & 0xff); b[7] = (unsigned int)(v1.w & 0xff);
    }
    unsigned long long o =
          (unsigned long long)b[0]         | ((unsigned long long)b[1] << 8)
        | ((unsigned long long)b[2] << 16) | ((unsigned long long)b[3] << 24)
        | ((unsigned long long)b[4] << 32) | ((unsigned long long)b[5] << 40)
        | ((unsigned long long)b[6] << 48) | ((unsigned long long)b[7] << 56);
    reinterpret_cast<unsigned long long*>(g_lab)[t] = o;

    float* mc = cnt + w * (CMAX * 32);
    #pragma unroll
    for (int i = 0; i < 8; ++i) mc[b[i] * 32 + l] += 1.f;
    __syncthreads();

    float tot = 0.f;
    #pragma unroll
    for (int j = 0; j < 32; ++j) tot += mc[l * 32 + ((l + j) & 31)];
    sbuf[w * 32 + l] = tot;
    __syncthreads();

    if (w == 0) {
        float s = 0.f;
        #pragma unroll
        for (int k = 0; k < 8; ++k) s += sbuf[k * 32 + l];
        const int n = (blockIdx.x * 2048) / P;
        atomicAdd(&g_cnts[n * CMAX + l], s);
    }
}

// ---------------------------------------------------------------------------
// Pass 1: segment sums, one co-resident wave (288 blocks, 2/SM).
// 16 warps; warp w streams channel w. Transposed bins [c][lane]: bank==lane,
// conflict-free, lane-private -> race-free. Unroll-8 front-batched loads.
// Last finishing block computes means + distance/regularizer terms.
__global__ void __launch_bounds__(512, 2) k_pass1(const float* __restrict__ x, int P) {
    __shared__ float bins[E_CH * CMAX * 32];   // 64KB
    __shared__ int s_last;
    const int n = blockIdx.y;
    const int tid = threadIdx.x;
    const int w = tid >> 5, l = tid & 31;

    for (int i = tid * 4; i < E_CH * CMAX * 32; i += 512 * 4)
        *reinterpret_cast<float4*>(bins + i) = make_float4(0.f, 0.f, 0.f, 0.f);
    __syncthreads();

    float* mb = bins + w * (CMAX * 32);

    const int base = blockIdx.x * CHUNK1;
    const float4* xp = reinterpret_cast<const float4*>(x + ((size_t)(n * E_CH + w)) * P + base);
    const unsigned int* lp = reinterpret_cast<const unsigned int*>(g_lab + (size_t)n * P + base);

    #pragma unroll 1
    for (int it = 0; it < (CHUNK1 >> 7); it += 8) {
        const int i0 = it * 32 + l;
        float4 v0 = xp[i0];
        float4 v1 = xp[i0 + 32];
        float4 v2 = xp[i0 + 64];
        float4 v3 = xp[i0 + 96];
        float4 v4 = xp[i0 + 128];
        float4 v5 = xp[i0 + 160];
        float4 v6 = xp[i0 + 192];
        float4 v7 = xp[i0 + 224];
        unsigned int u0 = lp[i0],       u1 = lp[i0 + 32],  u2 = lp[i0 + 64],  u3 = lp[i0 + 96];
        unsigned int u4 = lp[i0 + 128], u5 = lp[i0 + 160], u6 = lp[i0 + 192], u7 = lp[i0 + 224];

        mb[(u0 & 0xffu) * 32 + l] += v0.x; mb[((u0 >> 8) & 0xffu) * 32 + l] += v0.y;
        mb[((u0 >> 16) & 0xffu) * 32 + l] += v0.z; mb[(u0 >> 24) * 32 + l] += v0.w;
        mb[(u1 & 0xffu) * 32 + l] += v1.x; mb[((u1 >> 8) & 0xffu) * 32 + l] += v1.y;
        mb[((u1 >> 16) & 0xffu) * 32 + l] += v1.z; mb[(u1 >> 24) * 32 + l] += v1.w;
        mb[(u2 & 0xffu) * 32 + l] += v2.x; mb[((u2 >> 8) & 0xffu) * 32 + l] += v2.y;
        mb[((u2 >> 16) & 0xffu) * 32 + l] += v2.z; mb[(u2 >> 24) * 32 + l] += v2.w;
        mb[(u3 & 0xffu) * 32 + l] += v3.x; mb[((u3 >> 8) & 0xffu) * 32 + l] += v3.y;
        mb[((u3 >> 16) & 0xffu) * 32 + l] += v3.z; mb[(u3 >> 24) * 32 + l] += v3.w;
        mb[(u4 & 0xffu) * 32 + l] += v4.x; mb[((u4 >> 8) & 0xffu) * 32 + l] += v4.y;
        mb[((u4 >> 16) & 0xffu) * 32 + l] += v4.z; mb[(u4 >> 24) * 32 + l] += v4.w;
        mb[(u5 & 0xffu) * 32 + l] += v5.x; mb[((u5 >> 8) & 0xffu) * 32 + l] += v5.y;
        mb[((u5 >> 16) & 0xffu) * 32 + l] += v5.z; mb[(u5 >> 24) * 32 + l] += v5.w;
        mb[(u6 & 0xffu) * 32 + l] += v6.x; mb[((u6 >> 8) & 0xffu) * 32 + l] += v6.y;
        mb[((u6 >> 16) & 0xffu) * 32 + l] += v6.z; mb[(u6 >> 24) * 32 + l] += v6.w;
        mb[(u7 & 0xffu) * 32 + l] += v7.x; mb[((u7 >> 8) & 0xffu) * 32 + l] += v7.y;
        mb[((u7 >> 16) & 0xffu) * 32 + l] += v7.z; mb[(u7 >> 24) * 32 + l] += v7.w;
    }
    __syncwarp();

    float tot = 0.f;
    #pragma unroll
    for (int j = 0; j < 32; ++j)
        tot += mb[l * 32 + ((l + j) & 31)];
    atomicAdd(&g_sums[(n * CMAX + l) * E_CH + w], tot);

    // ---- last-block handoff: compute means + distance/reg terms ----
    __threadfence();
    __syncthreads();
    if (tid == 0) {
        unsigned int old = atomicAdd(&g_done1, 1u);
        s_last = (old == gridDim.x * gridDim.y - 1) ? 1 : 0;
    }
    __syncthreads();
    if (!s_last) return;

    float* sm   = bins;          // reuse smem as scratch
    float* red  = bins + 512;
    float* red2 = bins + 1024;
    const float rep = 2.0f * 2.0f;   // 2 * DELTA_DIST

    for (int img = 0; img < N_IMG; ++img) {
        {
            int c = tid / E_CH;
            float cntv = fmaxf(g_cnts[img * CMAX + c], 1.f);
            float mval = g_sums[img * CMAX * E_CH + tid] / cntv;
            sm[tid] = mval;
            g_means[img * CMAX * E_CH + tid] = mval;
        }
        __syncthreads();

        float dl = 0.f, rl = 0.f;
        for (int t2 = tid; t2 < CMAX * CMAX; t2 += 512) {
            int i = t2 >> 5, j = t2 & 31;
            if (i != j) {
                float s = 0.f;
                #pragma unroll
                for (int e = 0; e < E_CH; ++e) {
                    float d = sm[i * E_CH + e] - sm[j * E_CH + e];
                    s += d * d;
                }
                float dist = sqrtf(fmaxf(s, 1e-12f));
                float h = fmaxf(rep - dist, 0.f);
                dl += h * h;
            }
        }
        if (tid < CMAX) {
            float s = 0.f;
            #pragma unroll
            for (int e = 0; e < E_CH; ++e) { float mv = sm[tid * E_CH + e]; s += mv * mv; }
            rl = sqrtf(fmaxf(s, 1e-12f));
        }
        __syncthreads();     // sm reads done before red overwrite region? (disjoint but safe)
        red[tid] = dl; red2[tid] = rl;
        __syncthreads();
        for (int st = 256; st > 0; st >>= 1) {
            if (tid < st) { red[tid] += red[tid + st]; red2[tid] += red2[tid + st]; }
            __syncthreads();
        }
        if (tid == 0)
            g_aux[img] = red[0] / (float)(CMAX * (CMAX - 1)) + 0.001f * red2[0] / (float)CMAX;
        __syncthreads();
    }
    if (tid == 0) g_done1 = 0;   // reset for next graph replay
}

// ---------------------------------------------------------------------------
// Variance term, merged over images via blockIdx.y. Lane l holds mean[l][*] +
// inv_count[l]; gathers via shfl.idx. Last block writes d_out + cleanup.
__global__ void __launch_bounds__(256) k_var(const float* __restrict__ x, int P,
                                             float* __restrict__ out) {
    __shared__ float wred[8];
    __shared__ int s_last;
    const int n = blockIdx.y;
    const int tid = threadIdx.x;
    const int l = tid & 31;

    float m[E_CH];
    {
        const float4* gm = reinterpret_cast<const float4*>(g_means + (n * CMAX + l) * E_CH);
        float4* mm = reinterpret_cast<float4*>(m);
        mm[0] = gm[0]; mm[1] = gm[1]; mm[2] = gm[2]; mm[3] = gm[3];
    }
    float sinv = 1.0f / fmaxf(g_cnts[n * CMAX + l], 1.f);

    const int p0 = blockIdx.x * 1024 + tid * 4;
    unsigned int u = *reinterpret_cast<const unsigned int*>(g_lab + (size_t)n * P + p0);
    const int c0 = u & 0xffu, c1 = (u >> 8) & 0xffu, c2 = (u >> 16) & 0xffu, c3 = u >> 24;
    const float* xb = x + (size_t)n * E_CH * P + p0;

    float d0 = 0.f, d1 = 0.f, d2 = 0.f, d3 = 0.f;
    #pragma unroll
    for (int e = 0; e < E_CH; ++e) {
        float4 v = *reinterpret_cast<const float4*>(xb + (size_t)e * P);
        float t;
        t = v.x - __shfl_sync(0xffffffffu, m[e], c0); d0 += t * t;
        t = v.y - __shfl_sync(0xffffffffu, m[e], c1); d1 += t * t;
        t = v.z - __shfl_sync(0xffffffffu, m[e], c2); d2 += t * t;
        t = v.w - __shfl_sync(0xffffffffu, m[e], c3); d3 += t * t;
    }

    float acc = 0.f, dd, h;
    dd = sqrtf(fmaxf(d0, 1e-12f)); h = fmaxf(dd - 0.5f, 0.f);
    acc += h * h * __shfl_sync(0xffffffffu, sinv, c0);
    dd = sqrtf(fmaxf(d1, 1e-12f)); h = fmaxf(dd - 0.5f, 0.f);
    acc += h * h * __shfl_sync(0xffffffffu, sinv, c1);
    dd = sqrtf(fmaxf(d2, 1e-12f)); h = fmaxf(dd - 0.5f, 0.f);
    acc += h * h * __shfl_sync(0xffffffffu, sinv, c2);
    dd = sqrtf(fmaxf(d3, 1e-12f)); h = fmaxf(dd - 0.5f, 0.f);
    acc += h * h * __shfl_sync(0xffffffffu, sinv, c3);

    #pragma unroll
    for (int off = 16; off; off >>= 1) acc += __shfl_down_sync(0xffffffffu, acc, off);
    if (l == 0) wred[tid >> 5] = acc;
    __syncthreads();
    if (tid < 8) {
        float v = wred[tid];
        #pragma unroll
        for (int off = 4; off; off >>= 1) v += __shfl_down_sync(0xffu, v, off);
        if (tid == 0) atomicAdd(&g_var[n], v);
    }

    // ---- last-block handoff: final combine + cleanup for next replay ----
    __threadfence();
    __syncthreads();
    if (tid == 0) {
        unsigned int old = atomicAdd(&g_done2, 1u);
        s_last = (old == gridDim.x * gridDim.y - 1) ? 1 : 0;
    }
    __syncthreads();
    if (!s_last) return;

    if (tid == 0) {
        float s = 0.f;
        #pragma unroll
        for (int img = 0; img < N_IMG; ++img)
            s += g_var[img] / (float)CMAX + g_aux[img];
        out[0] = s / (float)N_IMG;
        g_done2 = 0;
    }
    __syncthreads();
    for (int i = tid; i < N_IMG * CMAX * E_CH; i += 256) g_sums[i] = 0.f;
    if (tid < N_IMG * CMAX) g_cnts[tid] = 0.f;
    if (tid < N_IMG) g_var[tid] = 0.f;
}

// ---------------------------------------------------------------------------
extern "C" void kernel_launch(void* const* d_in, const int* in_sizes, int n_in,
                              void* d_out, int out_size) {
    const float* x   = (const float*)d_in[0];
    const void*  tgt = d_in[1];

    const int NP = in_sizes[1];      // N * H * W
    const int P  = NP / N_IMG;

    k_convert<<<(NP + 2047) / 2048, 256>>>(tgt, NP, P);

    dim3 g1((P + CHUNK1 - 1) / CHUNK1, N_IMG);
    k_pass1<<<g1, 512>>>(x, P);

    dim3 g2((P + 1023) / 1024, N_IMG);
    k_var<<<g2, 256>>>(x, P, (float*)d_out);
}